// round 16
// baseline (speedup 1.0000x reference)
#include <cuda_runtime.h>
#include <math.h>

#define NN      8192
#define KZ      20
#define PDIM    20
#define NVZ     64
#define NUMPROT 20
#define FZ      256
#define NFEAT   2000
#define NDIST   100
#define NBUCK   4096

// output layout: tuple members concatenated, float32
#define OFF_POS (NN*(FZ+NVZ))
#define OFF_NP  (OFF_POS + NN*3)
#define OFF_ND  (OFF_NP  + NN*KZ*3)
#define OFF_EI  (OFF_ND  + NN*KZ*PDIM)
#define OFF_FEI (OFF_EI  + NN*KZ)

typedef unsigned long long u64;

// device scratch (allocation-free rule -> static globals)
__device__ float4 g_pos4[NN];
__device__ float4 g_spos4[NN];   // z-bucket-sorted positions (+n2)
__device__ int    g_sidx[NN];    // sorted pos -> original index
__device__ int    g_hist[NBUCK];
__device__ int    g_off[NBUCK];
__device__ float4 g_ncac[NN*3];
__device__ int    g_edge[NN*KZ];
__device__ float  g_dist[NN*NDIST];
__device__ float  g_wt[NFEAT*NVZ];
__device__ float  g_freq[PDIM/2];
__device__ int    g_mask_kind;

__device__ __forceinline__ u64 ffma2(u64 a, u64 b, u64 c) {
    u64 d;
    asm("fma.rn.f32x2 %0, %1, %2, %3;" : "=l"(d) : "l"(a), "l"(b), "l"(c));
    return d;
}
__device__ __forceinline__ u64 pack2(float x, float y) {
    u64 r;
    asm("mov.b64 %0, {%1, %2};" : "=l"(r) : "f"(x), "f"(y));
    return r;
}
__device__ __forceinline__ void unpack2(u64 v, float& x, float& y) {
    asm("mov.b64 {%0, %1}, %2;" : "=f"(x), "=f"(y) : "l"(v));
}

__device__ __forceinline__ int zbucket(float z) {
    int b = (int)((z + 16.0f) * 128.0f);   // 4096 buckets over [-16,16]
    return min(max(b, 0), NBUCK-1);
}

// ---------------------------------------------------------------------------
// FMA-pipe sincos (abs err < 4e-6 for |x| < 25)
// ---------------------------------------------------------------------------
__device__ __forceinline__ void sincos_poly(float x, float& so, float& co) {
    float q = rintf(x * 0.6366197723675814f);
    int iq = (int)q;
    float r = fmaf(-q, 1.57079637050628662109375f, x);
    r = fmaf(-q, -4.37113900018624283e-8f, r);
    float r2 = r * r;
    float ps = fmaf(-1.9841270114e-4f, r2, 8.3333337680e-3f);
    ps = fmaf(ps, r2, -1.6666667163e-1f);
    float sinr = fmaf(ps * r2, r, r);
    float pc = fmaf(-1.3888889225e-3f, r2, 4.1666667908e-2f);
    pc = fmaf(pc, r2, -0.5f);
    float cosr = fmaf(pc, r2, 1.0f);
    int qq = iq & 3;
    float s_ = (qq & 1) ? cosr : sinr;
    float c_ = (qq & 1) ? sinr : cosr;
    if (qq == 1 || qq == 2) c_ = -c_;
    if (qq >= 2) s_ = -s_;
    so = s_; co = c_;
}

// ---------------------------------------------------------------------------
// Classify prot_mask + freqs + zero the z-histogram.
// ---------------------------------------------------------------------------
__global__ void detect_kernel(const unsigned int* __restrict__ m) {
    __shared__ int red[256];
    int t = threadIdx.x;
    int code = 0;
    for (int i = t; i < 2048; i += 256) {
        unsigned w = m[i];
        if (w == 0x3F800000u) code = 2;
        else if (w != 0u && w != 1u) code = max(code, 1);
    }
    red[t] = code; __syncthreads();
    for (int s = 128; s > 0; s >>= 1) {
        if (t < s) red[t] = max(red[t], red[t+s]);
        __syncthreads();
    }
    if (t == 0) g_mask_kind = red[0];
    if (t < PDIM/2) g_freq[t] = (float)exp(-0.39120230054281463 * (double)t);
    for (int i = t; i < NBUCK; i += 256) g_hist[i] = 0;
}

// ne_weight (64,2000) -> g_wt (2000,64)
__global__ void wt_kernel(const float* __restrict__ w) {
    int idx = blockIdx.x*256 + threadIdx.x;
    if (idx >= NVZ*NFEAT) return;
    int o = idx / NFEAT, f = idx - o*NFEAT;
    g_wt[f*NVZ + o] = w[idx];
}

// per-node: pos4 (pos + |p|^2), ncac atoms, positions out, z-histogram
__global__ void setup_kernel(const float* __restrict__ aff,
                             const float* __restrict__ lit,
                             const void*  __restrict__ maskp,
                             float* __restrict__ out) {
    int i = blockIdx.x*256 + threadIdx.x;
    if (i >= NN) return;
    const float* A = aff + i*12;
    float r0=A[0], r1=A[1], r2=A[2],  tx=A[3];
    float r3=A[4], r4=A[5], r5=A[6],  ty=A[7];
    float r6=A[8], r7=A[9], r8=A[10], tz=A[11];
    float n2 = __fadd_rn(__fadd_rn(__fmul_rn(tx,tx), __fmul_rn(ty,ty)),
                         __fmul_rn(tz,tz));
    g_pos4[i] = make_float4(tx,ty,tz,n2);
    out[OFF_POS+i*3+0]=tx; out[OFF_POS+i*3+1]=ty; out[OFF_POS+i*3+2]=tz;
    atomicAdd(&g_hist[zbucket(tz)], 1);

    int kind = g_mask_kind;
    bool mk;
    if (kind == 1)      mk = ((const unsigned char*)maskp)[i] != 0;
    else if (kind == 2) mk = ((const float*)maskp)[i] != 0.0f;
    else                mk = ((const int*)maskp)[i] != 0;
    const float* L = lit + (mk ? 0 : NUMPROT)*9;
    #pragma unroll
    for (int a = 0; a < 3; a++) {
        float lx=L[a*3+0], ly=L[a*3+1], lz=L[a*3+2];
        float px = fmaf(r0,lx, fmaf(r1,ly, r2*lz)) + tx;
        float py = fmaf(r3,lx, fmaf(r4,ly, r5*lz)) + ty;
        float pz = fmaf(r6,lx, fmaf(r7,ly, r8*lz)) + tz;
        g_ncac[i*3+a] = make_float4(px,py,pz,0.f);
    }
}

// exclusive prefix over 4096 bucket counts (1 block, 1024 threads)
__global__ void prefix_kernel() {
    __shared__ int s[1024];
    int t = threadIdx.x;
    int a0 = g_hist[t*4+0], a1 = g_hist[t*4+1];
    int a2 = g_hist[t*4+2], a3 = g_hist[t*4+3];
    int sum = a0+a1+a2+a3;
    s[t] = sum;
    __syncthreads();
    for (int off = 1; off < 1024; off <<= 1) {
        int v = (t >= off) ? s[t-off] : 0;
        __syncthreads();
        s[t] += v;
        __syncthreads();
    }
    int excl = s[t] - sum;
    g_off[t*4+0] = excl;
    g_off[t*4+1] = excl + a0;
    g_off[t*4+2] = excl + a0 + a1;
    g_off[t*4+3] = excl + a0 + a1 + a2;
}

// scatter into z-sorted order (within-bucket order arbitrary -> harmless,
// final top-20 is lexicographic-unique and scan-order invariant)
__global__ void scatter_kernel() {
    int i = blockIdx.x*256 + threadIdx.x;
    if (i >= NN) return;
    float4 p = g_pos4[i];
    int b = zbucket(p.z);
    int pos = atomicAdd(&g_off[b], 1);
    g_spos4[pos] = p;
    g_sidx[pos]  = i;
}

// ---------------------------------------------------------------------------
// kNN, z-window pruned, queries processed in SORTED order: warp handles
// sorted position sp -> all 8 warps of a block walk the same window (L1 line
// reuse x8, balanced trip counts). Exact: same frozen d2 bits, lexicographic
// (d2,index) lane-distributed insert is scan-order invariant.
//   dot = fma(z,z', fma(y,y', rn(x*x')));  d2 = rn(n2i + fma(-2,dot,n2j))
// Side exit: closest possible remaining z-dist exceeds thr (+margin, since
// (dz)^2 <= true d2 and |computed-true| <= few ulp).
// ---------------------------------------------------------------------------
__global__ void __launch_bounds__(256) knn_kernel(float* __restrict__ out) {
    const unsigned FULL = 0xffffffffu;
    int warp = threadIdx.x >> 5;
    int lane = threadIdx.x & 31;
    int sp = blockIdx.x*8 + warp;       // sorted position
    int q  = g_sidx[sp];                // original index
    float4 P = g_spos4[sp];
    float zq = P.z;
    const float INF = __int_as_float(0x7f800000);
    const float W = 0.0085f;            // > bucket width 32/4096
    float dist = INF;
    int   idx  = 0x7FFFFFFF;
    float thrd = INF;

    int cR = sp >> 5;
    int cL = cR - 1;
    bool doneR = false;
    bool doneL = (cL < 0);

    while (!doneR || !doneL) {
        if (!doneR) {
            int base = cR << 5;
            float4 c = g_spos4[base + lane];
            float dot = __fmaf_rn(P.z, c.z,
                        __fmaf_rn(P.y, c.y, __fmul_rn(P.x, c.x)));
            float d2  = __fadd_rn(P.w, __fmaf_rn(-2.0f, dot, c.w));
            unsigned bal = __ballot_sync(FULL, d2 <= thrd);
            if (bal) {
                do {
                    int src = __ffs(bal) - 1; bal &= bal - 1;
                    float cd = __shfl_sync(FULL, d2, src);
                    int   ci = g_sidx[base + src];
                    if (ci != q) {
                        unsigned mlt = __ballot_sync(FULL,
                            (dist < cd) || (dist == cd && idx < ci)) & 0xFFFFFu;
                        int p = __popc(mlt);
                        if (p < 20) {
                            float nd = __shfl_up_sync(FULL, dist, 1);
                            int   ni = __shfl_up_sync(FULL, idx, 1);
                            if (lane >= p && lane < 20) {
                                dist = (lane == p) ? cd : nd;
                                idx  = (lane == p) ? ci : ni;
                            }
                        }
                    }
                } while (bal);
                thrd = __shfl_sync(FULL, dist, 19);
            }
            float zhi = __shfl_sync(FULL, c.z, 31);
            float dz = zhi - zq - W;
            if (dz > 0.f && dz*dz > __fmaf_rn(thrd, 1.0001f, 1e-5f)) doneR = true;
            cR++;
            if (cR >= NN/32) doneR = true;
        }
        if (!doneL) {
            int base = cL << 5;
            float4 c = g_spos4[base + lane];
            float dot = __fmaf_rn(P.z, c.z,
                        __fmaf_rn(P.y, c.y, __fmul_rn(P.x, c.x)));
            float d2  = __fadd_rn(P.w, __fmaf_rn(-2.0f, dot, c.w));
            unsigned bal = __ballot_sync(FULL, d2 <= thrd);
            if (bal) {
                do {
                    int src = __ffs(bal) - 1; bal &= bal - 1;
                    float cd = __shfl_sync(FULL, d2, src);
                    int   ci = g_sidx[base + src];
                    if (ci != q) {
                        unsigned mlt = __ballot_sync(FULL,
                            (dist < cd) || (dist == cd && idx < ci)) & 0xFFFFFu;
                        int p = __popc(mlt);
                        if (p < 20) {
                            float nd = __shfl_up_sync(FULL, dist, 1);
                            int   ni = __shfl_up_sync(FULL, idx, 1);
                            if (lane >= p && lane < 20) {
                                dist = (lane == p) ? cd : nd;
                                idx  = (lane == p) ? ci : ni;
                            }
                        }
                    }
                } while (bal);
                thrd = __shfl_sync(FULL, dist, 19);
            }
            float zlo = __shfl_sync(FULL, c.z, 0);
            float dz = zq - zlo - W;
            if (dz > 0.f && dz*dz > __fmaf_rn(thrd, 1.0001f, 1e-5f)) doneL = true;
            cL--;
            if (cL < 0) doneL = true;
        }
    }
    if (lane < KZ) {
        g_edge[q*KZ+lane] = idx;
        out[OFF_EI  + q*KZ + lane] = (float)idx;
        out[OFF_FEI + q*KZ + lane] = (float)idx;
        out[OFF_FEI + NN*KZ + q*KZ + lane] = (float)q;
    }
}

// ---------------------------------------------------------------------------
// Per-edge geometry, 8 nodes per 256-thread block (warp per node, 20 lanes).
// ---------------------------------------------------------------------------
__global__ void __launch_bounds__(256) geom_kernel(const float* __restrict__ aff,
                                                   float* __restrict__ out) {
    int n = blockIdx.x*8 + (threadIdx.x >> 5);
    int k = threadIdx.x & 31;
    if (k >= KZ) return;
    const float* A = aff + n*12;
    float r0=A[0], r1=A[1], r2=A[2],  tx=A[3];
    float r3=A[4], r4=A[5], r5=A[6],  ty=A[7];
    float r6=A[8], r7=A[9], r8=A[10], tz=A[11];
    int j = g_edge[n*KZ+k];
    float4 nb = g_pos4[j];
    float vx = nb.x - tx, vy = nb.y - ty, vz = nb.z - tz;
    float ex = fmaf(r0,vx, fmaf(r3,vy, r6*vz));
    float ey = fmaf(r1,vx, fmaf(r4,vy, r7*vz));
    float ez = fmaf(r2,vx, fmaf(r5,vy, r8*vz));
    int eb = (n*KZ+k)*3;
    out[OFF_NP+eb+0]=ex; out[OFF_NP+eb+1]=ey; out[OFF_NP+eb+2]=ez;
    float nrm = sqrtf(fmaf(ex,ex, fmaf(ey,ey, ez*ez)));
    int db = (n*KZ+k)*PDIM;
    #pragma unroll
    for (int t = 0; t < PDIM/2; t++) {
        float sv, cv;
        sincos_poly(nrm * g_freq[t], sv, cv);
        out[OFF_ND+db+t]    = sv;
        out[OFF_ND+db+10+t] = cv;
    }
    float4 ca = g_ncac[n*3+1], np = g_ncac[n*3+0], cp = g_ncac[n*3+2];
    #pragma unroll
    for (int a = 0; a < 3; a++) {
        float4 p = g_ncac[j*3+a];
        float dx=p.x-ca.x, dy=p.y-ca.y, dz=p.z-ca.z;
        g_dist[n*NDIST + k*3 + a] = sqrtf(fmaf(dx,dx, fmaf(dy,dy, dz*dz)));
    }
    {
        float4 p = g_ncac[j*3+2];
        float dx=p.x-np.x, dy=p.y-np.y, dz=p.z-np.z;
        g_dist[n*NDIST + 60 + k] = sqrtf(fmaf(dx,dx, fmaf(dy,dy, dz*dz)));
        float4 p2 = g_ncac[j*3+0];
        float ex2=p2.x-cp.x, ey2=p2.y-cp.y, ez2=p2.z-cp.z;
        g_dist[n*NDIST + 80 + k] = sqrtf(fmaf(ex2,ex2, fmaf(ey2,ey2, ez2*ez2)));
    }
}

// ---------------------------------------------------------------------------
// Fused enc+GEMM (+x copy). A-tile generated in smem from staged distances.
// ---------------------------------------------------------------------------
#define GBK 20
__global__ void __launch_bounds__(256) gemm_kernel(const float* __restrict__ x,
                                                   float* __restrict__ out) {
    __shared__ __align__(16) float dl[NDIST][65];
    __shared__ __align__(16) float fl[PDIM/2];
    __shared__ __align__(16) float As[GBK][68];
    __shared__ __align__(16) float Bs[2][GBK][64];
    int tid = threadIdx.x;
    int tx = tid & 15, ty = tid >> 4;
    int m0 = blockIdx.x * 64;

    {
        const float4* xs = (const float4*)(x) + (size_t)m0*64;
        float4* od = (float4*)out;
        #pragma unroll
        for (int i = 0; i < 16; i++) {
            int e = tid + i*256;
            int r = e >> 6, c = e & 63;
            od[(size_t)(m0+r)*80 + c] = xs[e];
        }
    }

    if (tid < PDIM/2) fl[tid] = g_freq[tid];
    for (int i = tid; i < 64*NDIST; i += 256) {
        int m = i / NDIST, d = i - m*NDIST;
        dl[d][m] = g_dist[(size_t)(m0+m)*NDIST + d];
    }
    #pragma unroll
    for (int i = 0; i < 5; i++) {
        int e = tid + i*256;
        Bs[0][e>>6][e&63] = g_wt[(e>>6)*NVZ + (e&63)];
    }
    __syncthreads();

    u64 acc[4][2];
    #pragma unroll
    for (int a = 0; a < 4; a++) { acc[a][0] = pack2(0.f,0.f); acc[a][1] = pack2(0.f,0.f); }

    for (int d = 0; d < NDIST; d++) {
        int cur = d & 1;
        float pb[5];
        if (d < NDIST-1) {
            #pragma unroll
            for (int i = 0; i < 5; i++) {
                int e = tid + i*256;
                pb[i] = g_wt[((d+1)*GBK + (e>>6))*NVZ + (e&63)];
            }
        }
        for (int f = tid; f < 640; f += 256) {
            int m = f & 63, t = f >> 6;
            float sv, cv;
            sincos_poly(dl[d][m] * fl[t], sv, cv);
            As[t][m]    = sv;
            As[t+10][m] = cv;
        }
        __syncthreads();
        #pragma unroll
        for (int kk = 0; kk < GBK; kk++) {
            float4 a = *(const float4*)&As[kk][ty*4];
            const u64* bp = (const u64*)&Bs[cur][kk][tx*4];
            u64 b01 = bp[0], b23 = bp[1];
            float av[4] = {a.x,a.y,a.z,a.w};
            #pragma unroll
            for (int i = 0; i < 4; i++) {
                u64 ai = pack2(av[i], av[i]);
                acc[i][0] = ffma2(ai, b01, acc[i][0]);
                acc[i][1] = ffma2(ai, b23, acc[i][1]);
            }
        }
        __syncthreads();
        if (d < NDIST-1) {
            #pragma unroll
            for (int i = 0; i < 5; i++) {
                int e = tid + i*256;
                Bs[cur^1][e>>6][e&63] = pb[i];
            }
        }
    }
    #pragma unroll
    for (int i = 0; i < 4; i++) {
        int m = m0 + ty*4 + i;
        float c0,c1,c2,c3;
        unpack2(acc[i][0], c0, c1);
        unpack2(acc[i][1], c2, c3);
        float* od = out + (size_t)m*(FZ+NVZ) + FZ + tx*4;
        od[0]=c0; od[1]=c1; od[2]=c2; od[3]=c3;
    }
}

extern "C" void kernel_launch(void* const* d_in, const int* in_sizes, int n_in,
                              void* d_out, int out_size) {
    const float* x    = (const float*)d_in[0];
    const float* aff  = (const float*)d_in[1];
    const float* nw   = (const float*)d_in[2];
    const float* lit  = (const float*)d_in[3];
    const void*  mask = d_in[4];
    float* out = (float*)d_out;

    detect_kernel<<<1, 256>>>((const unsigned int*)mask);
    wt_kernel<<<(NVZ*NFEAT + 255)/256, 256>>>(nw);
    setup_kernel<<<(NN+255)/256, 256>>>(aff, lit, mask, out);
    prefix_kernel<<<1, 1024>>>();
    scatter_kernel<<<(NN+255)/256, 256>>>();
    knn_kernel<<<NN/8, 256>>>(out);
    geom_kernel<<<NN/8, 256>>>(aff, out);
    gemm_kernel<<<NN/64, 256>>>(x, out);
}

// round 17
// speedup vs baseline: 1.0208x; 1.0208x over previous
#include <cuda_runtime.h>
#include <math.h>

#define NN      8192
#define KZ      20
#define PDIM    20
#define NVZ     64
#define NUMPROT 20
#define FZ      256
#define NFEAT   2000
#define NDIST   100
#define NBUCK   4096

// output layout: tuple members concatenated, float32
#define OFF_POS (NN*(FZ+NVZ))
#define OFF_NP  (OFF_POS + NN*3)
#define OFF_ND  (OFF_NP  + NN*KZ*3)
#define OFF_EI  (OFF_ND  + NN*KZ*PDIM)
#define OFF_FEI (OFF_EI  + NN*KZ)

typedef unsigned long long u64;

// device scratch (allocation-free rule -> static globals)
__device__ float4 g_pos4[NN];
__device__ float4 g_spos4[NN];   // z-bucket-sorted positions (+n2)
__device__ int    g_sidx[NN];    // sorted pos -> original index
__device__ int    g_hist[NBUCK];
__device__ int    g_off[NBUCK];
__device__ int    g_done;
__device__ float4 g_ncac[NN*3];
__device__ int    g_edge[NN*KZ];
__device__ float  g_dist[NN*NDIST];
__device__ float  g_wt[NFEAT*NVZ];
__device__ float  g_freq[PDIM/2];
__device__ int    g_mask_kind;

__device__ __forceinline__ u64 ffma2(u64 a, u64 b, u64 c) {
    u64 d;
    asm("fma.rn.f32x2 %0, %1, %2, %3;" : "=l"(d) : "l"(a), "l"(b), "l"(c));
    return d;
}
__device__ __forceinline__ u64 pack2(float x, float y) {
    u64 r;
    asm("mov.b64 %0, {%1, %2};" : "=l"(r) : "f"(x), "f"(y));
    return r;
}
__device__ __forceinline__ void unpack2(u64 v, float& x, float& y) {
    asm("mov.b64 {%0, %1}, %2;" : "=f"(x), "=f"(y) : "l"(v));
}

__device__ __forceinline__ int zbucket(float z) {
    int b = (int)((z + 16.0f) * 128.0f);   // 4096 buckets over [-16,16]
    return min(max(b, 0), NBUCK-1);
}

// ---------------------------------------------------------------------------
// FMA-pipe sincos (abs err < 4e-6 for |x| < 25)
// ---------------------------------------------------------------------------
__device__ __forceinline__ void sincos_poly(float x, float& so, float& co) {
    float q = rintf(x * 0.6366197723675814f);
    int iq = (int)q;
    float r = fmaf(-q, 1.57079637050628662109375f, x);
    r = fmaf(-q, -4.37113900018624283e-8f, r);
    float r2 = r * r;
    float ps = fmaf(-1.9841270114e-4f, r2, 8.3333337680e-3f);
    ps = fmaf(ps, r2, -1.6666667163e-1f);
    float sinr = fmaf(ps * r2, r, r);
    float pc = fmaf(-1.3888889225e-3f, r2, 4.1666667908e-2f);
    pc = fmaf(pc, r2, -0.5f);
    float cosr = fmaf(pc, r2, 1.0f);
    int qq = iq & 3;
    float s_ = (qq & 1) ? cosr : sinr;
    float c_ = (qq & 1) ? sinr : cosr;
    if (qq == 1 || qq == 2) c_ = -c_;
    if (qq >= 2) s_ = -s_;
    so = s_; co = c_;
}

// ---------------------------------------------------------------------------
// init: block 0 classifies prot_mask, computes freqs, zeroes hist + ticket;
// all blocks grid-stride the ne_weight transpose.
// ---------------------------------------------------------------------------
__global__ void init_kernel(const unsigned int* __restrict__ m,
                            const float* __restrict__ w) {
    int t = threadIdx.x;
    if (blockIdx.x == 0) {
        __shared__ int red[256];
        int code = 0;
        for (int i = t; i < 2048; i += 256) {
            unsigned wv = m[i];
            if (wv == 0x3F800000u) code = 2;
            else if (wv != 0u && wv != 1u) code = max(code, 1);
        }
        red[t] = code; __syncthreads();
        for (int s = 128; s > 0; s >>= 1) {
            if (t < s) red[t] = max(red[t], red[t+s]);
            __syncthreads();
        }
        if (t == 0) { g_mask_kind = red[0]; g_done = 0; }
        if (t < PDIM/2) g_freq[t] = (float)exp(-0.39120230054281463 * (double)t);
        for (int i = t; i < NBUCK; i += 256) g_hist[i] = 0;
    }
    for (int idx = blockIdx.x*256 + t; idx < NVZ*NFEAT; idx += gridDim.x*256) {
        int o = idx / NFEAT, f = idx - o*NFEAT;
        g_wt[f*NVZ + o] = w[idx];
    }
}

// ---------------------------------------------------------------------------
// per-node setup (pos4, ncac, positions out, z-histogram); the LAST block to
// finish also computes the exclusive prefix over the 4096 bucket counts.
// ---------------------------------------------------------------------------
__global__ void __launch_bounds__(256) setup_kernel(const float* __restrict__ aff,
                                                    const float* __restrict__ lit,
                                                    const void*  __restrict__ maskp,
                                                    float* __restrict__ out) {
    int i = blockIdx.x*256 + threadIdx.x;   // grid is exactly NN/256
    {
        const float* A = aff + i*12;
        float r0=A[0], r1=A[1], r2=A[2],  tx=A[3];
        float r3=A[4], r4=A[5], r5=A[6],  ty=A[7];
        float r6=A[8], r7=A[9], r8=A[10], tz=A[11];
        float n2 = __fadd_rn(__fadd_rn(__fmul_rn(tx,tx), __fmul_rn(ty,ty)),
                             __fmul_rn(tz,tz));
        g_pos4[i] = make_float4(tx,ty,tz,n2);
        out[OFF_POS+i*3+0]=tx; out[OFF_POS+i*3+1]=ty; out[OFF_POS+i*3+2]=tz;
        atomicAdd(&g_hist[zbucket(tz)], 1);

        int kind = g_mask_kind;
        bool mk;
        if (kind == 1)      mk = ((const unsigned char*)maskp)[i] != 0;
        else if (kind == 2) mk = ((const float*)maskp)[i] != 0.0f;
        else                mk = ((const int*)maskp)[i] != 0;
        const float* L = lit + (mk ? 0 : NUMPROT)*9;
        #pragma unroll
        for (int a = 0; a < 3; a++) {
            float lx=L[a*3+0], ly=L[a*3+1], lz=L[a*3+2];
            float px = fmaf(r0,lx, fmaf(r1,ly, r2*lz)) + tx;
            float py = fmaf(r3,lx, fmaf(r4,ly, r5*lz)) + ty;
            float pz = fmaf(r6,lx, fmaf(r7,ly, r8*lz)) + tz;
            g_ncac[i*3+a] = make_float4(px,py,pz,0.f);
        }
    }
    // last-block-does-prefix
    __threadfence();
    __shared__ int ticket;
    if (threadIdx.x == 0) ticket = atomicAdd(&g_done, 1);
    __syncthreads();
    if (ticket == gridDim.x - 1) {
        __shared__ int psum[256];
        int t = threadIdx.x;
        int base = t*16;
        int loc[16];
        int s = 0;
        #pragma unroll
        for (int k = 0; k < 16; k++) { loc[k] = s; s += g_hist[base+k]; }
        psum[t] = s;
        __syncthreads();
        for (int off = 1; off < 256; off <<= 1) {
            int v = (t >= off) ? psum[t-off] : 0;
            __syncthreads();
            psum[t] += v;
            __syncthreads();
        }
        int excl = psum[t] - s;
        #pragma unroll
        for (int k = 0; k < 16; k++) g_off[base+k] = excl + loc[k];
    }
}

// scatter into z-sorted order (within-bucket order arbitrary -> harmless,
// final top-20 is lexicographic-unique and scan-order invariant)
__global__ void scatter_kernel() {
    int i = blockIdx.x*256 + threadIdx.x;
    if (i >= NN) return;
    float4 p = g_pos4[i];
    int b = zbucket(p.z);
    int pos = atomicAdd(&g_off[b], 1);
    g_spos4[pos] = p;
    g_sidx[pos]  = i;
}

// ---------------------------------------------------------------------------
// kNN, z-window pruned, sorted-order queries. Candidate ORIGINAL indices are
// co-loaded per lane (coalesced) and shuffled in the insert path — no
// dependent scalar LDG inside the serial insert chain.
// d2 bits FROZEN: dot = fma(z,z', fma(y,y', rn(x*x')));
//                 d2  = rn(n2i + fma(-2,dot,n2j))
// Lexicographic (d2, original-index) lane-distributed top-20 == lax.top_k.
// ---------------------------------------------------------------------------
__global__ void __launch_bounds__(256) knn_kernel(float* __restrict__ out) {
    const unsigned FULL = 0xffffffffu;
    int warp = threadIdx.x >> 5;
    int lane = threadIdx.x & 31;
    int sp = blockIdx.x*8 + warp;       // sorted position
    int q  = g_sidx[sp];                // original index
    float4 P = g_spos4[sp];
    float zq = P.z;
    const float INF = __int_as_float(0x7f800000);
    const float W = 0.0085f;            // > bucket width 32/4096
    float dist = INF;
    int   idx  = 0x7FFFFFFF;
    float thrd = INF;

    int cR = sp >> 5;
    int cL = cR - 1;
    bool doneR = false;
    bool doneL = (cL < 0);

    while (!doneR || !doneL) {
        if (!doneR) {
            int base = cR << 5;
            float4 c = g_spos4[base + lane];
            int  myci = g_sidx[base + lane];
            float dot = __fmaf_rn(P.z, c.z,
                        __fmaf_rn(P.y, c.y, __fmul_rn(P.x, c.x)));
            float d2  = __fadd_rn(P.w, __fmaf_rn(-2.0f, dot, c.w));
            unsigned bal = __ballot_sync(FULL, d2 <= thrd);
            if (bal) {
                do {
                    int src = __ffs(bal) - 1; bal &= bal - 1;
                    float cd = __shfl_sync(FULL, d2, src);
                    int   ci = __shfl_sync(FULL, myci, src);
                    if (ci != q) {
                        unsigned mlt = __ballot_sync(FULL,
                            (dist < cd) || (dist == cd && idx < ci)) & 0xFFFFFu;
                        int p = __popc(mlt);
                        if (p < 20) {
                            float nd = __shfl_up_sync(FULL, dist, 1);
                            int   ni = __shfl_up_sync(FULL, idx, 1);
                            if (lane >= p && lane < 20) {
                                dist = (lane == p) ? cd : nd;
                                idx  = (lane == p) ? ci : ni;
                            }
                        }
                    }
                } while (bal);
                thrd = __shfl_sync(FULL, dist, 19);
            }
            float zhi = __shfl_sync(FULL, c.z, 31);
            float dz = zhi - zq - W;
            if (dz > 0.f && dz*dz > __fmaf_rn(thrd, 1.0001f, 1e-5f)) doneR = true;
            cR++;
            if (cR >= NN/32) doneR = true;
        }
        if (!doneL) {
            int base = cL << 5;
            float4 c = g_spos4[base + lane];
            int  myci = g_sidx[base + lane];
            float dot = __fmaf_rn(P.z, c.z,
                        __fmaf_rn(P.y, c.y, __fmul_rn(P.x, c.x)));
            float d2  = __fadd_rn(P.w, __fmaf_rn(-2.0f, dot, c.w));
            unsigned bal = __ballot_sync(FULL, d2 <= thrd);
            if (bal) {
                do {
                    int src = __ffs(bal) - 1; bal &= bal - 1;
                    float cd = __shfl_sync(FULL, d2, src);
                    int   ci = __shfl_sync(FULL, myci, src);
                    if (ci != q) {
                        unsigned mlt = __ballot_sync(FULL,
                            (dist < cd) || (dist == cd && idx < ci)) & 0xFFFFFu;
                        int p = __popc(mlt);
                        if (p < 20) {
                            float nd = __shfl_up_sync(FULL, dist, 1);
                            int   ni = __shfl_up_sync(FULL, idx, 1);
                            if (lane >= p && lane < 20) {
                                dist = (lane == p) ? cd : nd;
                                idx  = (lane == p) ? ci : ni;
                            }
                        }
                    }
                } while (bal);
                thrd = __shfl_sync(FULL, dist, 19);
            }
            float zlo = __shfl_sync(FULL, c.z, 0);
            float dz = zq - zlo - W;
            if (dz > 0.f && dz*dz > __fmaf_rn(thrd, 1.0001f, 1e-5f)) doneL = true;
            cL--;
            if (cL < 0) doneL = true;
        }
    }
    if (lane < KZ) {
        g_edge[q*KZ+lane] = idx;
        out[OFF_EI  + q*KZ + lane] = (float)idx;
        out[OFF_FEI + q*KZ + lane] = (float)idx;
        out[OFF_FEI + NN*KZ + q*KZ + lane] = (float)q;
    }
}

// ---------------------------------------------------------------------------
// Per-edge geometry, 8 nodes per 256-thread block (warp per node, 20 lanes).
// ---------------------------------------------------------------------------
__global__ void __launch_bounds__(256) geom_kernel(const float* __restrict__ aff,
                                                   float* __restrict__ out) {
    int n = blockIdx.x*8 + (threadIdx.x >> 5);
    int k = threadIdx.x & 31;
    if (k >= KZ) return;
    const float* A = aff + n*12;
    float r0=A[0], r1=A[1], r2=A[2],  tx=A[3];
    float r3=A[4], r4=A[5], r5=A[6],  ty=A[7];
    float r6=A[8], r7=A[9], r8=A[10], tz=A[11];
    int j = g_edge[n*KZ+k];
    float4 nb = g_pos4[j];
    float vx = nb.x - tx, vy = nb.y - ty, vz = nb.z - tz;
    float ex = fmaf(r0,vx, fmaf(r3,vy, r6*vz));
    float ey = fmaf(r1,vx, fmaf(r4,vy, r7*vz));
    float ez = fmaf(r2,vx, fmaf(r5,vy, r8*vz));
    int eb = (n*KZ+k)*3;
    out[OFF_NP+eb+0]=ex; out[OFF_NP+eb+1]=ey; out[OFF_NP+eb+2]=ez;
    float nrm = sqrtf(fmaf(ex,ex, fmaf(ey,ey, ez*ez)));
    int db = (n*KZ+k)*PDIM;
    #pragma unroll
    for (int t = 0; t < PDIM/2; t++) {
        float sv, cv;
        sincos_poly(nrm * g_freq[t], sv, cv);
        out[OFF_ND+db+t]    = sv;
        out[OFF_ND+db+10+t] = cv;
    }
    float4 ca = g_ncac[n*3+1], np = g_ncac[n*3+0], cp = g_ncac[n*3+2];
    #pragma unroll
    for (int a = 0; a < 3; a++) {
        float4 p = g_ncac[j*3+a];
        float dx=p.x-ca.x, dy=p.y-ca.y, dz=p.z-ca.z;
        g_dist[n*NDIST + k*3 + a] = sqrtf(fmaf(dx,dx, fmaf(dy,dy, dz*dz)));
    }
    {
        float4 p = g_ncac[j*3+2];
        float dx=p.x-np.x, dy=p.y-np.y, dz=p.z-np.z;
        g_dist[n*NDIST + 60 + k] = sqrtf(fmaf(dx,dx, fmaf(dy,dy, dz*dz)));
        float4 p2 = g_ncac[j*3+0];
        float ex2=p2.x-cp.x, ey2=p2.y-cp.y, ez2=p2.z-cp.z;
        g_dist[n*NDIST + 80 + k] = sqrtf(fmaf(ex2,ex2, fmaf(ey2,ey2, ez2*ez2)));
    }
}

// ---------------------------------------------------------------------------
// Fused enc+GEMM (+x copy). A-tile generated in smem from staged distances.
// 16B-aligned shared arrays (LDS.128). Bitwise identical embedding.
// ---------------------------------------------------------------------------
#define GBK 20
__global__ void __launch_bounds__(256) gemm_kernel(const float* __restrict__ x,
                                                   float* __restrict__ out) {
    __shared__ __align__(16) float dl[NDIST][65];
    __shared__ __align__(16) float fl[PDIM/2];
    __shared__ __align__(16) float As[GBK][68];
    __shared__ __align__(16) float Bs[2][GBK][64];
    int tid = threadIdx.x;
    int tx = tid & 15, ty = tid >> 4;
    int m0 = blockIdx.x * 64;

    {
        const float4* xs = (const float4*)(x) + (size_t)m0*64;
        float4* od = (float4*)out;
        #pragma unroll
        for (int i = 0; i < 16; i++) {
            int e = tid + i*256;
            int r = e >> 6, c = e & 63;
            od[(size_t)(m0+r)*80 + c] = xs[e];
        }
    }

    if (tid < PDIM/2) fl[tid] = g_freq[tid];
    for (int i = tid; i < 64*NDIST; i += 256) {
        int m = i / NDIST, d = i - m*NDIST;
        dl[d][m] = g_dist[(size_t)(m0+m)*NDIST + d];
    }
    #pragma unroll
    for (int i = 0; i < 5; i++) {
        int e = tid + i*256;
        Bs[0][e>>6][e&63] = g_wt[(e>>6)*NVZ + (e&63)];
    }
    __syncthreads();

    u64 acc[4][2];
    #pragma unroll
    for (int a = 0; a < 4; a++) { acc[a][0] = pack2(0.f,0.f); acc[a][1] = pack2(0.f,0.f); }

    for (int d = 0; d < NDIST; d++) {
        int cur = d & 1;
        float pb[5];
        if (d < NDIST-1) {
            #pragma unroll
            for (int i = 0; i < 5; i++) {
                int e = tid + i*256;
                pb[i] = g_wt[((d+1)*GBK + (e>>6))*NVZ + (e&63)];
            }
        }
        for (int f = tid; f < 640; f += 256) {
            int m = f & 63, t = f >> 6;
            float sv, cv;
            sincos_poly(dl[d][m] * fl[t], sv, cv);
            As[t][m]    = sv;
            As[t+10][m] = cv;
        }
        __syncthreads();
        #pragma unroll
        for (int kk = 0; kk < GBK; kk++) {
            float4 a = *(const float4*)&As[kk][ty*4];
            const u64* bp = (const u64*)&Bs[cur][kk][tx*4];
            u64 b01 = bp[0], b23 = bp[1];
            float av[4] = {a.x,a.y,a.z,a.w};
            #pragma unroll
            for (int i = 0; i < 4; i++) {
                u64 ai = pack2(av[i], av[i]);
                acc[i][0] = ffma2(ai, b01, acc[i][0]);
                acc[i][1] = ffma2(ai, b23, acc[i][1]);
            }
        }
        __syncthreads();
        if (d < NDIST-1) {
            #pragma unroll
            for (int i = 0; i < 5; i++) {
                int e = tid + i*256;
                Bs[cur^1][e>>6][e&63] = pb[i];
            }
        }
    }
    #pragma unroll
    for (int i = 0; i < 4; i++) {
        int m = m0 + ty*4 + i;
        float c0,c1,c2,c3;
        unpack2(acc[i][0], c0, c1);
        unpack2(acc[i][1], c2, c3);
        float* od = out + (size_t)m*(FZ+NVZ) + FZ + tx*4;
        od[0]=c0; od[1]=c1; od[2]=c2; od[3]=c3;
    }
}

extern "C" void kernel_launch(void* const* d_in, const int* in_sizes, int n_in,
                              void* d_out, int out_size) {
    const float* x    = (const float*)d_in[0];
    const float* aff  = (const float*)d_in[1];
    const float* nw   = (const float*)d_in[2];
    const float* lit  = (const float*)d_in[3];
    const void*  mask = d_in[4];
    float* out = (float*)d_out;

    init_kernel<<<500, 256>>>((const unsigned int*)mask, nw);
    setup_kernel<<<NN/256, 256>>>(aff, lit, mask, out);
    scatter_kernel<<<NN/256, 256>>>();
    knn_kernel<<<NN/8, 256>>>(out);
    geom_kernel<<<NN/8, 256>>>(aff, out);
    gemm_kernel<<<NN/64, 256>>>(x, out);
}